// round 2
// baseline (speedup 1.0000x reference)
#include <cuda_runtime.h>
#include <math_constants.h>

#define WIN   400
#define RNUM  64
#define BNUM  2
#define ANUM  3
#define KSEL  8
#define NV4   (WIN / 4)   // 100 float4 per window row
#define RPW   8           // refs per warp

__global__ __launch_bounds__(256) void win_topk_kernel(
    const float* __restrict__ mixed,    // [B, S]
    const float* __restrict__ ref,      // [A, R, S]
    const float* __restrict__ weights,  // [K]
    float* __restrict__ out,            // [6*W] scores ++ [6*W*K] idx (as float)
    int S, int W, int write_idx)
{
    const int w    = blockIdx.x;
    const int a    = blockIdx.y;
    const int tid  = threadIdx.x;
    const int warp = tid >> 5;
    const int lane = tid & 31;

    __shared__ __align__(16) float sm_mixed[BNUM][WIN];
    __shared__ float sm_scores[BNUM][RNUM];
    __shared__ float sm_w[KSEL];

    const long base = (long)w * WIN;

    // Stage mixed tile (both batch rows) into shared, vectorized.
    {
        const float4* m4 = (const float4*)mixed;  // S % 4 == 0, base % 4 == 0
        float4* sm4 = (float4*)&sm_mixed[0][0];
        const int nv = BNUM * NV4;  // 200 float4
        for (int i = tid; i < nv; i += blockDim.x) {
            int b = i / NV4, v = i % NV4;
            sm4[b * NV4 + v] = m4[((long)b * S + base) / 4 + v];
        }
        if (tid < KSEL) sm_w[tid] = weights[tid];
    }
    __syncthreads();

    // Each warp streams 8 ref rows; per-lane partial sums, NO reduction in loop.
    {
        const float4* sm0 = (const float4*)&sm_mixed[0][0];
        const float4* sm1 = (const float4*)&sm_mixed[1][0];
        const float* refa = ref + ((long)a * RNUM + warp * RPW) * S + base;

        // Cache this lane's mixed slice in registers (3 full + predicated tail).
        float4 m00 = sm0[lane],      m01 = sm0[lane + 32], m02 = sm0[lane + 64];
        float4 m10 = sm1[lane],      m11 = sm1[lane + 32], m12 = sm1[lane + 64];
        float4 m03 = make_float4(0.f, 0.f, 0.f, 0.f);
        float4 m13 = make_float4(0.f, 0.f, 0.f, 0.f);
        const bool has_tail = (lane < NV4 - 96);   // lanes 0..3
        if (has_tail) { m03 = sm0[96 + lane]; m13 = sm1[96 + lane]; }

        float s0[RPW], s1[RPW];

        #pragma unroll
        for (int i = 0; i < RPW; i++) {
            const float4* row4 = (const float4*)(refa + (long)i * S);
            float4 rv0 = __ldcs(&row4[lane]);
            float4 rv1 = __ldcs(&row4[lane + 32]);
            float4 rv2 = __ldcs(&row4[lane + 64]);
            float4 rv3 = make_float4(0.f, 0.f, 0.f, 0.f);
            if (has_tail) rv3 = __ldcs(&row4[96 + lane]);

            float a0 = rv0.x * m00.x, b0 = rv0.y * m00.y;
            a0 = fmaf(rv0.z, m00.z, a0); b0 = fmaf(rv0.w, m00.w, b0);
            a0 = fmaf(rv1.x, m01.x, a0); b0 = fmaf(rv1.y, m01.y, b0);
            a0 = fmaf(rv1.z, m01.z, a0); b0 = fmaf(rv1.w, m01.w, b0);
            a0 = fmaf(rv2.x, m02.x, a0); b0 = fmaf(rv2.y, m02.y, b0);
            a0 = fmaf(rv2.z, m02.z, a0); b0 = fmaf(rv2.w, m02.w, b0);
            a0 = fmaf(rv3.x, m03.x, a0); b0 = fmaf(rv3.y, m03.y, b0);
            a0 = fmaf(rv3.z, m03.z, a0); b0 = fmaf(rv3.w, m03.w, b0);
            s0[i] = a0 + b0;

            float a1 = rv0.x * m10.x, b1 = rv0.y * m10.y;
            a1 = fmaf(rv0.z, m10.z, a1); b1 = fmaf(rv0.w, m10.w, b1);
            a1 = fmaf(rv1.x, m11.x, a1); b1 = fmaf(rv1.y, m11.y, b1);
            a1 = fmaf(rv1.z, m11.z, a1); b1 = fmaf(rv1.w, m11.w, b1);
            a1 = fmaf(rv2.x, m12.x, a1); b1 = fmaf(rv2.y, m12.y, b1);
            a1 = fmaf(rv2.z, m12.z, a1); b1 = fmaf(rv2.w, m12.w, b1);
            a1 = fmaf(rv3.x, m13.x, a1); b1 = fmaf(rv3.y, m13.y, b1);
            a1 = fmaf(rv3.z, m13.z, a1); b1 = fmaf(rv3.w, m13.w, b1);
            s1[i] = a1 + b1;
        }

        // All reductions at the end (off the load critical path).
        #pragma unroll
        for (int i = 0; i < RPW; i++) {
            float t0 = s0[i], t1 = s1[i];
            #pragma unroll
            for (int off = 16; off > 0; off >>= 1) {
                t0 += __shfl_down_sync(0xffffffffu, t0, off);
                t1 += __shfl_down_sync(0xffffffffu, t1, off);
            }
            if (lane == 0) {
                sm_scores[0][warp * RPW + i] = t0 * (1.0f / WIN);
                sm_scores[1][warp * RPW + i] = t1 * (1.0f / WIN);
            }
        }
    }
    __syncthreads();

    // Top-K (K=8) over 64 refs, warps 0 and 1 handle b=0/1.
    if (warp < BNUM) {
        const int b = warp;
        float v0 = sm_scores[b][lane];
        float v1 = sm_scores[b][lane + 32];
        float acc = 0.f;

        const long ow    = ((long)b * ANUM + a) * W + w;
        const long ibase = (long)BNUM * ANUM * W + ow * KSEL;

        #pragma unroll
        for (int k = 0; k < KSEL; k++) {
            float bv; int bi;
            if (v0 >= v1) { bv = v0; bi = lane; }        // ties -> lower index
            else          { bv = v1; bi = lane + 32; }
            #pragma unroll
            for (int off = 16; off > 0; off >>= 1) {
                float ov = __shfl_xor_sync(0xffffffffu, bv, off);
                int   oi = __shfl_xor_sync(0xffffffffu, bi, off);
                if (ov > bv || (ov == bv && oi < bi)) { bv = ov; bi = oi; }
            }
            acc = fmaf(bv, sm_w[k], acc);
            if (write_idx && lane == 0) out[ibase + k] = (float)bi;
            if (bi == lane)      v0 = -CUDART_INF_F;
            if (bi == lane + 32) v1 = -CUDART_INF_F;
        }
        if (lane == 0) out[ow] = acc;
    }
}

extern "C" void kernel_launch(void* const* d_in, const int* in_sizes, int n_in,
                              void* d_out, int out_size) {
    const float* mixed   = (const float*)d_in[0];
    const float* ref     = (const float*)d_in[1];
    const float* weights = (const float*)d_in[2];
    float* out = (float*)d_out;

    const int S = in_sizes[0] / BNUM;      // 400000
    const int W = S / WIN;                 // 1000
    const int write_idx = (out_size >= BNUM * ANUM * W * (1 + KSEL)) ? 1 : 0;

    dim3 grid(W, ANUM);
    win_topk_kernel<<<grid, 256>>>(mixed, ref, weights, out, S, W, write_idx);
}

// round 3
// speedup vs baseline: 1.0744x; 1.0744x over previous
#include <cuda_runtime.h>
#include <math_constants.h>

#define WIN   400
#define RNUM  64
#define BNUM  2
#define ANUM  3
#define KSEL  8
#define NV4   (WIN / 4)   // 100 float4 per window row

__global__ __launch_bounds__(256, 8) void win_topk_kernel(
    const float* __restrict__ mixed,    // [B, S]
    const float* __restrict__ ref,      // [A, R, S]
    const float* __restrict__ weights,  // [K]
    float* __restrict__ out,            // [6*W] scores ++ [6*W*K] idx (as float)
    int S, int W, int write_idx)
{
    const int w    = blockIdx.x;
    const int a    = blockIdx.y;
    const int tid  = threadIdx.x;
    const int warp = tid >> 5;
    const int lane = tid & 31;

    __shared__ __align__(16) float sm_mixed[BNUM][WIN];
    __shared__ float sm_scores[BNUM][RNUM];
    __shared__ float sm_w[KSEL];

    const long base = (long)w * WIN;

    // Stage mixed tile (both batch rows) into shared, vectorized.
    {
        const float4* m4 = (const float4*)mixed;  // S % 4 == 0, base % 4 == 0
        float4* sm4 = (float4*)&sm_mixed[0][0];
        const int nv = BNUM * NV4;  // 200 float4
        for (int i = tid; i < nv; i += blockDim.x) {
            int b = i / NV4, v = i % NV4;
            sm4[b * NV4 + v] = m4[((long)b * S + base) / 4 + v];
        }
        if (tid < KSEL) sm_w[tid] = weights[tid];
    }
    __syncthreads();

    // Each warp computes windowed dot products for 8 ref rows (both batches).
    {
        const float4* sm0 = (const float4*)&sm_mixed[0][0];
        const float4* sm1 = (const float4*)&sm_mixed[1][0];
        const float* refa = ref + ((long)a * RNUM) * S + base;

        #pragma unroll
        for (int i = 0; i < RNUM / 8; i++) {
            const int r = warp * (RNUM / 8) + i;
            const float4* row4 = (const float4*)(refa + (long)r * S);

            float s0 = 0.f, s1 = 0.f;
            #pragma unroll
            for (int j = 0; j < 3; j++) {   // 96 vec4 covered by full warp
                int v = lane + j * 32;
                float4 rv = __ldg(&row4[v]);
                float4 m0 = sm0[v];
                float4 m1 = sm1[v];
                s0 = fmaf(rv.x, m0.x, s0); s0 = fmaf(rv.y, m0.y, s0);
                s0 = fmaf(rv.z, m0.z, s0); s0 = fmaf(rv.w, m0.w, s0);
                s1 = fmaf(rv.x, m1.x, s1); s1 = fmaf(rv.y, m1.y, s1);
                s1 = fmaf(rv.z, m1.z, s1); s1 = fmaf(rv.w, m1.w, s1);
            }
            if (lane < NV4 - 96) {          // tail: vec4 indices 96..99
                int v = 96 + lane;
                float4 rv = __ldg(&row4[v]);
                float4 m0 = sm0[v];
                float4 m1 = sm1[v];
                s0 = fmaf(rv.x, m0.x, s0); s0 = fmaf(rv.y, m0.y, s0);
                s0 = fmaf(rv.z, m0.z, s0); s0 = fmaf(rv.w, m0.w, s0);
                s1 = fmaf(rv.x, m1.x, s1); s1 = fmaf(rv.y, m1.y, s1);
                s1 = fmaf(rv.z, m1.z, s1); s1 = fmaf(rv.w, m1.w, s1);
            }
            // Warp reduction
            #pragma unroll
            for (int off = 16; off > 0; off >>= 1) {
                s0 += __shfl_down_sync(0xffffffffu, s0, off);
                s1 += __shfl_down_sync(0xffffffffu, s1, off);
            }
            if (lane == 0) {
                sm_scores[0][r] = s0 * (1.0f / WIN);
                sm_scores[1][r] = s1 * (1.0f / WIN);
            }
        }
    }
    __syncthreads();

    // Top-K (K=8) over 64 refs, warps 0 and 1 handle b=0/1.
    if (warp < BNUM) {
        const int b = warp;
        float v0 = sm_scores[b][lane];
        float v1 = sm_scores[b][lane + 32];
        float acc = 0.f;

        const long ow    = ((long)b * ANUM + a) * W + w;
        const long ibase = (long)BNUM * ANUM * W + ow * KSEL;

        #pragma unroll
        for (int k = 0; k < KSEL; k++) {
            float bv; int bi;
            if (v0 >= v1) { bv = v0; bi = lane; }        // ties -> lower index
            else          { bv = v1; bi = lane + 32; }
            #pragma unroll
            for (int off = 16; off > 0; off >>= 1) {
                float ov = __shfl_xor_sync(0xffffffffu, bv, off);
                int   oi = __shfl_xor_sync(0xffffffffu, bi, off);
                if (ov > bv || (ov == bv && oi < bi)) { bv = ov; bi = oi; }
            }
            acc = fmaf(bv, sm_w[k], acc);
            if (write_idx && lane == 0) out[ibase + k] = (float)bi;
            if (bi == lane)      v0 = -CUDART_INF_F;
            if (bi == lane + 32) v1 = -CUDART_INF_F;
        }
        if (lane == 0) out[ow] = acc;
    }
}

extern "C" void kernel_launch(void* const* d_in, const int* in_sizes, int n_in,
                              void* d_out, int out_size) {
    const float* mixed   = (const float*)d_in[0];
    const float* ref     = (const float*)d_in[1];
    const float* weights = (const float*)d_in[2];
    float* out = (float*)d_out;

    const int S = in_sizes[0] / BNUM;      // 400000
    const int W = S / WIN;                 // 1000
    const int write_idx = (out_size >= BNUM * ANUM * W * (1 + KSEL)) ? 1 : 0;

    dim3 grid(W, ANUM);
    win_topk_kernel<<<grid, 256>>>(mixed, ref, weights, out, S, W, write_idx);
}

// round 4
// speedup vs baseline: 1.1781x; 1.0965x over previous
#include <cuda_runtime.h>
#include <math_constants.h>

#define WIN   400
#define RNUM  64
#define BNUM  2
#define ANUM  3
#define KSEL  8
#define WPC   2                 // windows per CTA
#define SPAN  (WIN * WPC)       // 800 floats
#define NV4S  (SPAN / 4)        // 200 float4 per row span

__global__ __launch_bounds__(256) void win_topk_kernel(
    const float* __restrict__ mixed,    // [B, S]
    const float* __restrict__ ref,      // [A, R, S]
    const float* __restrict__ weights,  // [K]
    float* __restrict__ out,            // [6*W] scores ++ [6*W*K] idx (as float)
    int S, int W, int write_idx)
{
    const int wg   = blockIdx.x;        // window-pair index
    const int a    = blockIdx.y;
    const int tid  = threadIdx.x;
    const int warp = tid >> 5;
    const int lane = tid & 31;

    __shared__ __align__(16) float sm_mixed[BNUM][SPAN];
    __shared__ float sm_scores[BNUM][WPC][RNUM];
    __shared__ float sm_w[KSEL];

    const long base = (long)wg * SPAN;

    // Stage mixed span (both batch rows) into shared, vectorized.
    {
        const float4* m4 = (const float4*)mixed;  // S % 4 == 0, base % 4 == 0
        float4* sm4 = (float4*)&sm_mixed[0][0];
        const int nv = BNUM * NV4S;  // 400 float4
        for (int i = tid; i < nv; i += blockDim.x) {
            int b = i / NV4S, v = i % NV4S;
            sm4[b * NV4S + v] = m4[((long)b * S + base) / 4 + v];
        }
        if (tid < KSEL) sm_w[tid] = weights[tid];
    }
    __syncthreads();

    // Each warp streams 8 ref rows over the 3200B span (2 windows, 2 batches).
    {
        const float4* sm0 = (const float4*)&sm_mixed[0][0];
        const float4* sm1 = (const float4*)&sm_mixed[1][0];
        const float* refa = ref + ((long)a * RNUM) * S + base;

        #pragma unroll
        for (int i = 0; i < RNUM / 8; i++) {
            const int r = warp * (RNUM / 8) + i;
            const float4* row4 = (const float4*)(refa + (long)r * S);

            float s00 = 0.f, s01 = 0.f;   // batch0: win0, win1
            float s10 = 0.f, s11 = 0.f;   // batch1: win0, win1
            #pragma unroll
            for (int j = 0; j < 6; j++) {   // 192 vec4 full-warp
                int v = lane + j * 32;
                float4 rv = __ldg(&row4[v]);
                float4 m0 = sm0[v];
                float4 m1 = sm1[v];
                float c0 = rv.x * m0.x;
                c0 = fmaf(rv.y, m0.y, c0);
                c0 = fmaf(rv.z, m0.z, c0);
                c0 = fmaf(rv.w, m0.w, c0);
                float c1 = rv.x * m1.x;
                c1 = fmaf(rv.y, m1.y, c1);
                c1 = fmaf(rv.z, m1.z, c1);
                c1 = fmaf(rv.w, m1.w, c1);
                if (v < WIN / 4) { s00 += c0; s10 += c1; }
                else             { s01 += c0; s11 += c1; }
            }
            if (lane < NV4S - 192) {        // tail: vec4 192..199 (all win1)
                int v = 192 + lane;
                float4 rv = __ldg(&row4[v]);
                float4 m0 = sm0[v];
                float4 m1 = sm1[v];
                float c0 = rv.x * m0.x;
                c0 = fmaf(rv.y, m0.y, c0);
                c0 = fmaf(rv.z, m0.z, c0);
                c0 = fmaf(rv.w, m0.w, c0);
                float c1 = rv.x * m1.x;
                c1 = fmaf(rv.y, m1.y, c1);
                c1 = fmaf(rv.z, m1.z, c1);
                c1 = fmaf(rv.w, m1.w, c1);
                s01 += c0; s11 += c1;
            }
            // Warp reductions (4 values)
            #pragma unroll
            for (int off = 16; off > 0; off >>= 1) {
                s00 += __shfl_down_sync(0xffffffffu, s00, off);
                s01 += __shfl_down_sync(0xffffffffu, s01, off);
                s10 += __shfl_down_sync(0xffffffffu, s10, off);
                s11 += __shfl_down_sync(0xffffffffu, s11, off);
            }
            if (lane == 0) {
                sm_scores[0][0][r] = s00 * (1.0f / WIN);
                sm_scores[0][1][r] = s01 * (1.0f / WIN);
                sm_scores[1][0][r] = s10 * (1.0f / WIN);
                sm_scores[1][1][r] = s11 * (1.0f / WIN);
            }
        }
    }
    __syncthreads();

    // Top-K (K=8) over 64 refs; warps 0..3 handle (b, win) combos.
    if (warp < BNUM * WPC) {
        const int b   = warp >> 1;
        const int win = warp & 1;
        float v0 = sm_scores[b][win][lane];
        float v1 = sm_scores[b][win][lane + 32];
        float acc = 0.f;

        const int  wglob = wg * WPC + win;
        const long ow    = ((long)b * ANUM + a) * W + wglob;
        const long ibase = (long)BNUM * ANUM * W + ow * KSEL;

        #pragma unroll
        for (int k = 0; k < KSEL; k++) {
            float bv; int bi;
            if (v0 >= v1) { bv = v0; bi = lane; }        // ties -> lower index
            else          { bv = v1; bi = lane + 32; }
            #pragma unroll
            for (int off = 16; off > 0; off >>= 1) {
                float ov = __shfl_xor_sync(0xffffffffu, bv, off);
                int   oi = __shfl_xor_sync(0xffffffffu, bi, off);
                if (ov > bv || (ov == bv && oi < bi)) { bv = ov; bi = oi; }
            }
            acc = fmaf(bv, sm_w[k], acc);
            if (write_idx && lane == 0) out[ibase + k] = (float)bi;
            if (bi == lane)      v0 = -CUDART_INF_F;
            if (bi == lane + 32) v1 = -CUDART_INF_F;
        }
        if (lane == 0) out[ow] = acc;
    }
}

extern "C" void kernel_launch(void* const* d_in, const int* in_sizes, int n_in,
                              void* d_out, int out_size) {
    const float* mixed   = (const float*)d_in[0];
    const float* ref     = (const float*)d_in[1];
    const float* weights = (const float*)d_in[2];
    float* out = (float*)d_out;

    const int S = in_sizes[0] / BNUM;      // 400000
    const int W = S / WIN;                 // 1000
    const int write_idx = (out_size >= BNUM * ANUM * W * (1 + KSEL)) ? 1 : 0;

    dim3 grid(W / WPC, ANUM);
    win_topk_kernel<<<grid, 256>>>(mixed, ref, weights, out, S, W, write_idx);
}

// round 5
// speedup vs baseline: 1.1828x; 1.0040x over previous
#include <cuda_runtime.h>
#include <math_constants.h>

#define WIN   400
#define RNUM  64
#define BNUM  2
#define ANUM  3
#define KSEL  8
#define WPC   4                 // windows per CTA
#define SPAN  (WIN * WPC)       // 1600 floats
#define NV4S  (SPAN / 4)        // 400 float4 per row span
#define NFULL 12                // full warp-iterations (12*32 = 384)

__global__ __launch_bounds__(256, 6) void win_topk_kernel(
    const float* __restrict__ mixed,    // [B, S]
    const float* __restrict__ ref,      // [A, R, S]
    const float* __restrict__ weights,  // [K]
    float* __restrict__ out,            // [6*W] scores ++ [6*W*K] idx (as float)
    int S, int W, int write_idx)
{
    const int wg   = blockIdx.x;        // window-group index (4 windows)
    const int a    = blockIdx.y;
    const int tid  = threadIdx.x;
    const int warp = tid >> 5;
    const int lane = tid & 31;

    __shared__ __align__(16) float sm_mixed[BNUM][SPAN];
    __shared__ float sm_scores[BNUM][WPC][RNUM];
    __shared__ float sm_w[KSEL];

    const long base = (long)wg * SPAN;

    // Stage mixed span (both batch rows) into shared, vectorized.
    {
        const float4* m4 = (const float4*)mixed;  // S % 4 == 0, base % 4 == 0
        float4* sm4 = (float4*)&sm_mixed[0][0];
        const int nv = BNUM * NV4S;  // 800 float4
        for (int i = tid; i < nv; i += blockDim.x) {
            int b = i / NV4S, v = i % NV4S;
            sm4[b * NV4S + v] = m4[((long)b * S + base) / 4 + v];
        }
        if (tid < KSEL) sm_w[tid] = weights[tid];
    }
    __syncthreads();

    // Each warp streams 8 ref rows over the 6400B span (4 windows, 2 batches).
    {
        const float4* sm0 = (const float4*)&sm_mixed[0][0];
        const float4* sm1 = (const float4*)&sm_mixed[1][0];
        const float* refa = ref + ((long)a * RNUM) * S + base;

        #pragma unroll
        for (int i = 0; i < RNUM / 8; i++) {
            const int r = warp * (RNUM / 8) + i;
            const float4* row4 = (const float4*)(refa + (long)r * S);

            float sA[WPC] = {0.f, 0.f, 0.f, 0.f};   // batch 0, windows 0..3
            float sB[WPC] = {0.f, 0.f, 0.f, 0.f};   // batch 1, windows 0..3

            #pragma unroll
            for (int j = 0; j < NFULL; j++) {       // 384 vec4, full warp
                const int v = lane + j * 32;
                float4 rv = __ldg(&row4[v]);
                float4 m0 = sm0[v];
                float4 m1 = sm1[v];
                float c0 = rv.x * m0.x;
                c0 = fmaf(rv.y, m0.y, c0);
                c0 = fmaf(rv.z, m0.z, c0);
                c0 = fmaf(rv.w, m0.w, c0);
                float c1 = rv.x * m1.x;
                c1 = fmaf(rv.y, m1.y, c1);
                c1 = fmaf(rv.z, m1.z, c1);
                c1 = fmaf(rv.w, m1.w, c1);
                // Window boundaries at v = 100, 200, 300 (compile-time per j).
                const int wlo = (j * 32) / (WIN / 4);
                const int whi = (j * 32 + 31) / (WIN / 4);
                if (wlo == whi) {
                    sA[wlo] += c0; sB[wlo] += c1;
                } else if (v < whi * (WIN / 4)) {
                    sA[wlo] += c0; sB[wlo] += c1;
                } else {
                    sA[whi] += c0; sB[whi] += c1;
                }
            }
            if (lane < NV4S - NFULL * 32) {          // tail: v = 384..399, window 3
                const int v = NFULL * 32 + lane;
                float4 rv = __ldg(&row4[v]);
                float4 m0 = sm0[v];
                float4 m1 = sm1[v];
                float c0 = rv.x * m0.x;
                c0 = fmaf(rv.y, m0.y, c0);
                c0 = fmaf(rv.z, m0.z, c0);
                c0 = fmaf(rv.w, m0.w, c0);
                float c1 = rv.x * m1.x;
                c1 = fmaf(rv.y, m1.y, c1);
                c1 = fmaf(rv.z, m1.z, c1);
                c1 = fmaf(rv.w, m1.w, c1);
                sA[WPC - 1] += c0; sB[WPC - 1] += c1;
            }
            // Warp reductions (8 values)
            #pragma unroll
            for (int win = 0; win < WPC; win++) {
                #pragma unroll
                for (int off = 16; off > 0; off >>= 1) {
                    sA[win] += __shfl_down_sync(0xffffffffu, sA[win], off);
                    sB[win] += __shfl_down_sync(0xffffffffu, sB[win], off);
                }
            }
            if (lane == 0) {
                #pragma unroll
                for (int win = 0; win < WPC; win++) {
                    sm_scores[0][win][r] = sA[win] * (1.0f / WIN);
                    sm_scores[1][win][r] = sB[win] * (1.0f / WIN);
                }
            }
        }
    }
    __syncthreads();

    // Top-K (K=8) over 64 refs; warps 0..7 handle the 8 (b, win) combos.
    {
        const int b   = warp >> 2;
        const int win = warp & 3;
        float v0 = sm_scores[b][win][lane];
        float v1 = sm_scores[b][win][lane + 32];
        float acc = 0.f;

        const int  wglob = wg * WPC + win;
        const long ow    = ((long)b * ANUM + a) * W + wglob;
        const long ibase = (long)BNUM * ANUM * W + ow * KSEL;

        #pragma unroll
        for (int k = 0; k < KSEL; k++) {
            float bv; int bi;
            if (v0 >= v1) { bv = v0; bi = lane; }        // ties -> lower index
            else          { bv = v1; bi = lane + 32; }
            #pragma unroll
            for (int off = 16; off > 0; off >>= 1) {
                float ov = __shfl_xor_sync(0xffffffffu, bv, off);
                int   oi = __shfl_xor_sync(0xffffffffu, bi, off);
                if (ov > bv || (ov == bv && oi < bi)) { bv = ov; bi = oi; }
            }
            acc = fmaf(bv, sm_w[k], acc);
            if (write_idx && lane == 0) out[ibase + k] = (float)bi;
            if (bi == lane)      v0 = -CUDART_INF_F;
            if (bi == lane + 32) v1 = -CUDART_INF_F;
        }
        if (lane == 0) out[ow] = acc;
    }
}

extern "C" void kernel_launch(void* const* d_in, const int* in_sizes, int n_in,
                              void* d_out, int out_size) {
    const float* mixed   = (const float*)d_in[0];
    const float* ref     = (const float*)d_in[1];
    const float* weights = (const float*)d_in[2];
    float* out = (float*)d_out;

    const int S = in_sizes[0] / BNUM;      // 400000
    const int W = S / WIN;                 // 1000
    const int write_idx = (out_size >= BNUM * ANUM * W * (1 + KSEL)) ? 1 : 0;

    dim3 grid(W / WPC, ANUM);
    win_topk_kernel<<<grid, 256>>>(mixed, ref, weights, out, S, W, write_idx);
}